// round 1
// baseline (speedup 1.0000x reference)
#include <cuda_runtime.h>
#include <cuda_bf16.h>

// SentimentNetEnd2End: per-batch 512-step LSTM (I=H=3) + cosine sims vs two endings.
// One thread per batch element; weights in registers; float4-vectorized,
// software-pipelined input stream; accurate exp-based activations.

#define EPS 1e-8f

__device__ __forceinline__ float sigmoid_acc(float x) {
    // 1/(1+e^-x): FMUL + MUFU.EX2 + FADD + MUFU.RCP  (err ~1e-7)
    return 1.0f / (1.0f + __expf(-x));
}
__device__ __forceinline__ float tanh_acc(float x) {
    // tanh(x) = 2/(1+e^-2x) - 1
    float r = 1.0f / (1.0f + __expf(-2.0f * x));
    return 2.0f * r - 1.0f;
}

__global__ __launch_bounds__(64, 1)
void lstm_cos_kernel(const float* __restrict__ story,   // [B, T, 3]
                     const float* __restrict__ e1,      // [B, 3]
                     const float* __restrict__ e2,      // [B, 3]
                     const float* __restrict__ W_ih,    // [12, 3] (i,f,g,o)
                     const float* __restrict__ W_hh,    // [12, 3]
                     const float* __restrict__ b_ih,    // [12]
                     const float* __restrict__ b_hh,    // [12]
                     float* __restrict__ out,           // [B, 2]
                     int B, int T)
{
    int b = blockIdx.x * blockDim.x + threadIdx.x;
    if (b >= B) return;

    // ---- Weights into registers (L1/L2-broadcast reads, one-time) ----
    float wi[12][3], wh[12][3], bias[12];
#pragma unroll
    for (int r = 0; r < 12; r++) {
#pragma unroll
        for (int k = 0; k < 3; k++) {
            wi[r][k] = __ldg(&W_ih[r * 3 + k]);
            wh[r][k] = __ldg(&W_hh[r * 3 + k]);
        }
        bias[r] = __ldg(&b_ih[r]) + __ldg(&b_hh[r]);
    }

    // Per-thread input stream: T*3 floats, base offset b*T*3 floats = b*6144 bytes
    // (16B aligned for T=512). Read 4 steps (48B) per iteration as 3x float4.
    const float4* xp = reinterpret_cast<const float4*>(story + (size_t)b * (size_t)T * 3);

    float h0 = 0.f, h1 = 0.f, h2 = 0.f;
    float c0 = 0.f, c1 = 0.f, c2 = 0.f;

    // software pipeline: prefetch group 0
    float4 pA = xp[0], pB = xp[1], pC = xp[2];

    int ngroups = T >> 2;  // T divisible by 4
    for (int gidx = 0; gidx < ngroups; gidx++) {
        float x[12];
        x[0] = pA.x; x[1] = pA.y; x[2]  = pA.z; x[3]  = pA.w;
        x[4] = pB.x; x[5] = pB.y; x[6]  = pB.z; x[7]  = pB.w;
        x[8] = pC.x; x[9] = pC.y; x[10] = pC.z; x[11] = pC.w;

        if (gidx + 1 < ngroups) {
            int o = (gidx + 1) * 3;
            pA = xp[o]; pB = xp[o + 1]; pC = xp[o + 2];
        }

#pragma unroll
        for (int u = 0; u < 4; u++) {
            float x0 = x[u * 3 + 0], x1 = x[u * 3 + 1], x2 = x[u * 3 + 2];
            float g[12];
#pragma unroll
            for (int r = 0; r < 12; r++) {
                float acc = bias[r];
                acc = fmaf(wi[r][0], x0, acc);
                acc = fmaf(wi[r][1], x1, acc);
                acc = fmaf(wi[r][2], x2, acc);
                acc = fmaf(wh[r][0], h0, acc);
                acc = fmaf(wh[r][1], h1, acc);
                acc = fmaf(wh[r][2], h2, acc);
                g[r] = acc;
            }
            // gate order: i (0-2), f (3-5), g (6-8), o (9-11)
            float i0 = sigmoid_acc(g[0]), i1 = sigmoid_acc(g[1]), i2 = sigmoid_acc(g[2]);
            float f0 = sigmoid_acc(g[3]), f1 = sigmoid_acc(g[4]), f2 = sigmoid_acc(g[5]);
            float t0 = tanh_acc(g[6]),    t1 = tanh_acc(g[7]),    t2 = tanh_acc(g[8]);
            float o0 = sigmoid_acc(g[9]), o1 = sigmoid_acc(g[10]), o2 = sigmoid_acc(g[11]);

            c0 = fmaf(f0, c0, i0 * t0);
            c1 = fmaf(f1, c1, i1 * t1);
            c2 = fmaf(f2, c2, i2 * t2);

            h0 = o0 * tanh_acc(c0);
            h1 = o1 * tanh_acc(c1);
            h2 = o2 * tanh_acc(c2);
        }
    }

    // ---- Cosine similarities (torch CosineSimilarity semantics, eps=1e-8) ----
    float nh = sqrtf(h0 * h0 + h1 * h1 + h2 * h2);
    nh = fmaxf(nh, EPS);

    float a0 = e1[b * 3 + 0], a1 = e1[b * 3 + 1], a2 = e1[b * 3 + 2];
    float n1 = fmaxf(sqrtf(a0 * a0 + a1 * a1 + a2 * a2), EPS);
    float d1 = h0 * a0 + h1 * a1 + h2 * a2;

    float q0 = e2[b * 3 + 0], q1 = e2[b * 3 + 1], q2 = e2[b * 3 + 2];
    float n2 = fmaxf(sqrtf(q0 * q0 + q1 * q1 + q2 * q2), EPS);
    float d2 = h0 * q0 + h1 * q1 + h2 * q2;

    out[b * 2 + 0] = d1 / (nh * n1);
    out[b * 2 + 1] = d2 / (nh * n2);
}

extern "C" void kernel_launch(void* const* d_in, const int* in_sizes, int n_in,
                              void* d_out, int out_size) {
    const float* story = (const float*)d_in[0];  // [B, T, 3]
    const float* e1    = (const float*)d_in[1];  // [B, 3]
    const float* e2    = (const float*)d_in[2];  // [B, 3]
    const float* W_ih  = (const float*)d_in[3];  // [12, 3]
    const float* W_hh  = (const float*)d_in[4];  // [12, 3]
    const float* b_ih  = (const float*)d_in[5];  // [12]
    const float* b_hh  = (const float*)d_in[6];  // [12]
    float* out = (float*)d_out;                  // [B, 2]

    int B = in_sizes[1] / 3;
    int T = in_sizes[0] / (B * 3);

    int block = 64;
    int grid = (B + block - 1) / block;
    lstm_cos_kernel<<<grid, block>>>(story, e1, e2, W_ih, W_hh, b_ih, b_hh, out, B, T);
}

// round 13
// speedup vs baseline: 5.9037x; 5.9037x over previous
#include <cuda_runtime.h>
#include <cuda_bf16.h>
#include <cstdint>

// SentimentNetEnd2End: per-batch 512-step LSTM (I=H=3) + cosine sims vs two endings.
// One thread per batch element; weights in registers; float4-vectorized,
// software-pipelined input stream.
// R5: activations via single MUFU.TANH; sigmoid = 0.5*tanh(x/2)+0.5; block 128.
// R6: gate dot-products via packed fma.rn.f32x2 (FFMA2) -> 36 packed FMAs/step
//     instead of 72 scalar FFMA. Per-lane round-to-nearest == scalar fmaf,
//     so this change is numerics-exact.

#define EPS 1e-8f

__device__ __forceinline__ float fast_rcp(float x) {
    float y;
    asm("rcp.approx.f32 %0, %1;" : "=f"(y) : "f"(x));
    return y;
}
__device__ __forceinline__ float fast_tanh(float x) {
    float y;
    asm("tanh.approx.f32 %0, %1;" : "=f"(y) : "f"(x));
    return y;
}
__device__ __forceinline__ float sigmoid_f(float x) {
    // sigma(x) = 0.5*tanh(0.5x) + 0.5 : FMUL + MUFU.TANH + FFMA
    return fmaf(0.5f, fast_tanh(0.5f * x), 0.5f);
}

// ---- packed f32x2 helpers ----
__device__ __forceinline__ uint64_t pack2(float lo, float hi) {
    uint64_t d;
    asm("mov.b64 %0, {%1, %2};" : "=l"(d) : "f"(lo), "f"(hi));
    return d;
}
__device__ __forceinline__ void unpack2(uint64_t v, float& lo, float& hi) {
    asm("mov.b64 {%0, %1}, %2;" : "=f"(lo), "=f"(hi) : "l"(v));
}
__device__ __forceinline__ uint64_t ffma2(uint64_t a, uint64_t b, uint64_t c) {
    uint64_t d;
    asm("fma.rn.f32x2 %0, %1, %2, %3;" : "=l"(d) : "l"(a), "l"(b), "l"(c));
    return d;
}

__global__ __launch_bounds__(128, 1)
void lstm_cos_kernel(const float* __restrict__ story,   // [B, T, 3]
                     const float* __restrict__ e1,      // [B, 3]
                     const float* __restrict__ e2,      // [B, 3]
                     const float* __restrict__ W_ih,    // [12, 3] (i,f,g,o)
                     const float* __restrict__ W_hh,    // [12, 3]
                     const float* __restrict__ b_ih,    // [12]
                     const float* __restrict__ b_hh,    // [12]
                     float* __restrict__ out,           // [B, 2]
                     int B, int T)
{
    int b = blockIdx.x * blockDim.x + threadIdx.x;
    if (b >= B) return;

    // ---- Weights into registers, packed in gate pairs (2p, 2p+1) ----
    uint64_t pwi[6][3], pwh[6][3], pbias[6];
#pragma unroll
    for (int p = 0; p < 6; p++) {
        int r0 = 2 * p, r1 = 2 * p + 1;
#pragma unroll
        for (int k = 0; k < 3; k++) {
            pwi[p][k] = pack2(__ldg(&W_ih[r0 * 3 + k]), __ldg(&W_ih[r1 * 3 + k]));
            pwh[p][k] = pack2(__ldg(&W_hh[r0 * 3 + k]), __ldg(&W_hh[r1 * 3 + k]));
        }
        pbias[p] = pack2(__ldg(&b_ih[r0]) + __ldg(&b_hh[r0]),
                         __ldg(&b_ih[r1]) + __ldg(&b_hh[r1]));
    }

    // Per-thread input stream: T*3 floats, base offset b*6144 bytes (16B aligned).
    const float4* xp = reinterpret_cast<const float4*>(story + (size_t)b * (size_t)T * 3);

    float h0 = 0.f, h1 = 0.f, h2 = 0.f;
    float c0 = 0.f, c1 = 0.f, c2 = 0.f;

    // software pipeline: prefetch group 0 (4 timesteps = 3x float4)
    float4 pA = xp[0], pB = xp[1], pC = xp[2];

    int ngroups = T >> 2;
    for (int gidx = 0; gidx < ngroups; gidx++) {
        float x[12];
        x[0] = pA.x; x[1] = pA.y; x[2]  = pA.z; x[3]  = pA.w;
        x[4] = pB.x; x[5] = pB.y; x[6]  = pB.z; x[7]  = pB.w;
        x[8] = pC.x; x[9] = pC.y; x[10] = pC.z; x[11] = pC.w;

        if (gidx + 1 < ngroups) {
            int o = (gidx + 1) * 3;
            pA = xp[o]; pB = xp[o + 1]; pC = xp[o + 2];
        }

#pragma unroll
        for (int u = 0; u < 4; u++) {
            // broadcast-pack inputs and hidden state for this step
            uint64_t xx0 = pack2(x[u * 3 + 0], x[u * 3 + 0]);
            uint64_t xx1 = pack2(x[u * 3 + 1], x[u * 3 + 1]);
            uint64_t xx2 = pack2(x[u * 3 + 2], x[u * 3 + 2]);
            uint64_t hh0 = pack2(h0, h0);
            uint64_t hh1 = pack2(h1, h1);
            uint64_t hh2 = pack2(h2, h2);

            float g[12];
#pragma unroll
            for (int p = 0; p < 6; p++) {
                uint64_t acc = pbias[p];
                acc = ffma2(pwi[p][0], xx0, acc);
                acc = ffma2(pwi[p][1], xx1, acc);
                acc = ffma2(pwi[p][2], xx2, acc);
                acc = ffma2(pwh[p][0], hh0, acc);
                acc = ffma2(pwh[p][1], hh1, acc);
                acc = ffma2(pwh[p][2], hh2, acc);
                unpack2(acc, g[2 * p], g[2 * p + 1]);
            }
            // gate order: i (0-2), f (3-5), g (6-8), o (9-11)
            float i0 = sigmoid_f(g[0]),  i1 = sigmoid_f(g[1]),  i2 = sigmoid_f(g[2]);
            float f0 = sigmoid_f(g[3]),  f1 = sigmoid_f(g[4]),  f2 = sigmoid_f(g[5]);
            float t0 = fast_tanh(g[6]),  t1 = fast_tanh(g[7]),  t2 = fast_tanh(g[8]);
            float o0 = sigmoid_f(g[9]),  o1 = sigmoid_f(g[10]), o2 = sigmoid_f(g[11]);

            c0 = fmaf(f0, c0, i0 * t0);
            c1 = fmaf(f1, c1, i1 * t1);
            c2 = fmaf(f2, c2, i2 * t2);

            h0 = o0 * fast_tanh(c0);
            h1 = o1 * fast_tanh(c1);
            h2 = o2 * fast_tanh(c2);
        }
    }

    // ---- Cosine similarities (eps=1e-8) ----
    float nh2 = h0 * h0 + h1 * h1 + h2 * h2;
    float nh = fmaxf(sqrtf(nh2), EPS);

    float a0 = e1[b * 3 + 0], a1 = e1[b * 3 + 1], a2 = e1[b * 3 + 2];
    float n1 = fmaxf(sqrtf(a0 * a0 + a1 * a1 + a2 * a2), EPS);
    float d1 = h0 * a0 + h1 * a1 + h2 * a2;

    float q0 = e2[b * 3 + 0], q1 = e2[b * 3 + 1], q2 = e2[b * 3 + 2];
    float n2 = fmaxf(sqrtf(q0 * q0 + q1 * q1 + q2 * q2), EPS);
    float d2 = h0 * q0 + h1 * q1 + h2 * q2;

    out[b * 2 + 0] = d1 * fast_rcp(nh * n1);
    out[b * 2 + 1] = d2 * fast_rcp(nh * n2);
}

extern "C" void kernel_launch(void* const* d_in, const int* in_sizes, int n_in,
                              void* d_out, int out_size) {
    const float* story = (const float*)d_in[0];  // [B, T, 3]
    const float* e1    = (const float*)d_in[1];  // [B, 3]
    const float* e2    = (const float*)d_in[2];  // [B, 3]
    const float* W_ih  = (const float*)d_in[3];  // [12, 3]
    const float* W_hh  = (const float*)d_in[4];  // [12, 3]
    const float* b_ih  = (const float*)d_in[5];  // [12]
    const float* b_hh  = (const float*)d_in[6];  // [12]
    float* out = (float*)d_out;                  // [B, 2]

    int B = in_sizes[1] / 3;
    int T = in_sizes[0] / (B * 3);

    int block = 128;
    int grid = (B + block - 1) / block;
    lstm_cos_kernel<<<grid, block>>>(story, e1, e2, W_ih, W_hh, b_ih, b_hh, out, B, T);
}

// round 16
// speedup vs baseline: 6.0857x; 1.0308x over previous
#include <cuda_runtime.h>
#include <cuda_bf16.h>
#include <cstdint>

// SentimentNetEnd2End: per-batch 512-step LSTM (I=H=3) + cosine sims vs two endings.
// One thread per batch element (1 warp/SMSP chip-wide -> latency-bound regime).
// R6: packed fma.rn.f32x2 gates; MUFU.TANH activations; rcp.approx divisions.
// R14: latency-oriented scheduling.
//   - i/f/o weight rows pre-scaled by 0.5 (exact) -> sigmoid = fmaf(0.5,tanh(acc),0.5)
//     with no inner FMUL. 9 fewer FMA-pipe ops/step, shorter sigmoid chains.
//   - gate pairs reordered f,i,g,o so the c-critical chain (f,i,g -> c -> tanh c)
//     uses the earliest-issued MUFUs; o computed last (off the c-path).
//   - all 4 steps' x-projections hoisted into xacc[][] (h-independent FFMA2 pool
//     for the scheduler to interleave into recurrence stalls).

#define EPS 1e-8f

__device__ __forceinline__ float fast_rcp(float x) {
    float y;
    asm("rcp.approx.f32 %0, %1;" : "=f"(y) : "f"(x));
    return y;
}
__device__ __forceinline__ float fast_tanh(float x) {
    float y;
    asm("tanh.approx.f32 %0, %1;" : "=f"(y) : "f"(x));
    return y;
}

// ---- packed f32x2 helpers ----
__device__ __forceinline__ uint64_t pack2(float lo, float hi) {
    uint64_t d;
    asm("mov.b64 %0, {%1, %2};" : "=l"(d) : "f"(lo), "f"(hi));
    return d;
}
__device__ __forceinline__ void unpack2(uint64_t v, float& lo, float& hi) {
    asm("mov.b64 {%0, %1}, %2;" : "=f"(lo), "=f"(hi) : "l"(v));
}
__device__ __forceinline__ uint64_t ffma2(uint64_t a, uint64_t b, uint64_t c) {
    uint64_t d;
    asm("fma.rn.f32x2 %0, %1, %2, %3;" : "=l"(d) : "l"(a), "l"(b), "l"(c));
    return d;
}

__global__ __launch_bounds__(128, 1)
void lstm_cos_kernel(const float* __restrict__ story,   // [B, T, 3]
                     const float* __restrict__ e1,      // [B, 3]
                     const float* __restrict__ e2,      // [B, 3]
                     const float* __restrict__ W_ih,    // [12, 3] (i,f,g,o)
                     const float* __restrict__ W_hh,    // [12, 3]
                     const float* __restrict__ b_ih,    // [12]
                     const float* __restrict__ b_hh,    // [12]
                     float* __restrict__ out,           // [B, 2]
                     int B, int T)
{
    int b = blockIdx.x * blockDim.x + threadIdx.x;
    if (b >= B) return;

    // Pair layout (pair p holds rows rmap[2p], rmap[2p+1]), order f,i,g,o:
    //   q0..q2 = f gates, q3..q5 = i gates, q6..q8 = g gates, q9..q11 = o gates.
    // Rows 6..8 (g) unscaled; all sigmoid rows (i,f,o) pre-scaled by 0.5 (exact).
    const int rmap[12] = {3, 4, 5, 0, 1, 2, 6, 7, 8, 9, 10, 11};

    uint64_t pwi[6][3], pwh[6][3], pbias[6];
#pragma unroll
    for (int p = 0; p < 6; p++) {
        int r0 = rmap[2 * p], r1 = rmap[2 * p + 1];
        float s0 = (r0 >= 6 && r0 <= 8) ? 1.0f : 0.5f;
        float s1 = (r1 >= 6 && r1 <= 8) ? 1.0f : 0.5f;
#pragma unroll
        for (int k = 0; k < 3; k++) {
            pwi[p][k] = pack2(s0 * __ldg(&W_ih[r0 * 3 + k]), s1 * __ldg(&W_ih[r1 * 3 + k]));
            pwh[p][k] = pack2(s0 * __ldg(&W_hh[r0 * 3 + k]), s1 * __ldg(&W_hh[r1 * 3 + k]));
        }
        pbias[p] = pack2(s0 * (__ldg(&b_ih[r0]) + __ldg(&b_hh[r0])),
                         s1 * (__ldg(&b_ih[r1]) + __ldg(&b_hh[r1])));
    }

    // Per-thread input stream: T*3 floats, base offset b*6144 bytes (16B aligned).
    const float4* xp = reinterpret_cast<const float4*>(story + (size_t)b * (size_t)T * 3);

    float h0 = 0.f, h1 = 0.f, h2 = 0.f;
    float c0 = 0.f, c1 = 0.f, c2 = 0.f;

    // software pipeline: prefetch group 0 (4 timesteps = 3x float4)
    float4 pA = xp[0], pB = xp[1], pC = xp[2];

    int ngroups = T >> 2;
    for (int gidx = 0; gidx < ngroups; gidx++) {
        float x[12];
        x[0] = pA.x; x[1] = pA.y; x[2]  = pA.z; x[3]  = pA.w;
        x[4] = pB.x; x[5] = pB.y; x[6]  = pB.z; x[7]  = pB.w;
        x[8] = pC.x; x[9] = pC.y; x[10] = pC.z; x[11] = pC.w;

        if (gidx + 1 < ngroups) {
            int o = (gidx + 1) * 3;
            pA = xp[o]; pB = xp[o + 1]; pC = xp[o + 2];
        }

        // ---- h-independent x-projections for all 4 steps (pure ILP pool) ----
        uint64_t xacc[4][6];
#pragma unroll
        for (int u = 0; u < 4; u++) {
            uint64_t xx0 = pack2(x[u * 3 + 0], x[u * 3 + 0]);
            uint64_t xx1 = pack2(x[u * 3 + 1], x[u * 3 + 1]);
            uint64_t xx2 = pack2(x[u * 3 + 2], x[u * 3 + 2]);
#pragma unroll
            for (int p = 0; p < 6; p++) {
                uint64_t a = ffma2(pwi[p][0], xx0, pbias[p]);
                a = ffma2(pwi[p][1], xx1, a);
                xacc[u][p] = ffma2(pwi[p][2], xx2, a);
            }
        }

        // ---- serial recurrence: minimal h->h spine ----
#pragma unroll
        for (int u = 0; u < 4; u++) {
            uint64_t hh0 = pack2(h0, h0);
            uint64_t hh1 = pack2(h1, h1);
            uint64_t hh2 = pack2(h2, h2);

            float q[12];
#pragma unroll
            for (int p = 0; p < 6; p++) {
                uint64_t a = ffma2(pwh[p][0], hh0, xacc[u][p]);
                a = ffma2(pwh[p][1], hh1, a);
                a = ffma2(pwh[p][2], hh2, a);
                unpack2(a, q[2 * p], q[2 * p + 1]);
            }

            // critical c-chain first: f, i, g -> c -> tanh(c)
            float f0 = fmaf(0.5f, fast_tanh(q[0]), 0.5f);
            float f1 = fmaf(0.5f, fast_tanh(q[1]), 0.5f);
            float f2 = fmaf(0.5f, fast_tanh(q[2]), 0.5f);
            float i0 = fmaf(0.5f, fast_tanh(q[3]), 0.5f);
            float i1 = fmaf(0.5f, fast_tanh(q[4]), 0.5f);
            float i2 = fmaf(0.5f, fast_tanh(q[5]), 0.5f);
            float t0 = fast_tanh(q[6]);
            float t1 = fast_tanh(q[7]);
            float t2 = fast_tanh(q[8]);

            c0 = fmaf(f0, c0, i0 * t0);
            c1 = fmaf(f1, c1, i1 * t1);
            c2 = fmaf(f2, c2, i2 * t2);

            float tc0 = fast_tanh(c0);
            float tc1 = fast_tanh(c1);
            float tc2 = fast_tanh(c2);

            // o is off the c-path: compute last
            float o0 = fmaf(0.5f, fast_tanh(q[9]),  0.5f);
            float o1 = fmaf(0.5f, fast_tanh(q[10]), 0.5f);
            float o2 = fmaf(0.5f, fast_tanh(q[11]), 0.5f);

            h0 = o0 * tc0;
            h1 = o1 * tc1;
            h2 = o2 * tc2;
        }
    }

    // ---- Cosine similarities (eps=1e-8) ----
    float nh2 = h0 * h0 + h1 * h1 + h2 * h2;
    float nh = fmaxf(sqrtf(nh2), EPS);

    float a0 = e1[b * 3 + 0], a1 = e1[b * 3 + 1], a2 = e1[b * 3 + 2];
    float n1 = fmaxf(sqrtf(a0 * a0 + a1 * a1 + a2 * a2), EPS);
    float d1 = h0 * a0 + h1 * a1 + h2 * a2;

    float q0 = e2[b * 3 + 0], q1 = e2[b * 3 + 1], q2 = e2[b * 3 + 2];
    float n2 = fmaxf(sqrtf(q0 * q0 + q1 * q1 + q2 * q2), EPS);
    float d2 = h0 * q0 + h1 * q1 + h2 * q2;

    out[b * 2 + 0] = d1 * fast_rcp(nh * n1);
    out[b * 2 + 1] = d2 * fast_rcp(nh * n2);
}

extern "C" void kernel_launch(void* const* d_in, const int* in_sizes, int n_in,
                              void* d_out, int out_size) {
    const float* story = (const float*)d_in[0];  // [B, T, 3]
    const float* e1    = (const float*)d_in[1];  // [B, 3]
    const float* e2    = (const float*)d_in[2];  // [B, 3]
    const float* W_ih  = (const float*)d_in[3];  // [12, 3]
    const float* W_hh  = (const float*)d_in[4];  // [12, 3]
    const float* b_ih  = (const float*)d_in[5];  // [12]
    const float* b_hh  = (const float*)d_in[6];  // [12]
    float* out = (float*)d_out;                  // [B, 2]

    int B = in_sizes[1] / 3;
    int T = in_sizes[0] / (B * 3);

    int block = 128;
    int grid = (B + block - 1) / block;
    lstm_cos_kernel<<<grid, block>>>(story, e1, e2, W_ih, W_hh, b_ih, b_hh, out, B, T);
}